// round 10
// baseline (speedup 1.0000x reference)
#include <cuda_runtime.h>
#include <cstdint>

// BidPrefix: row = [rates[0..299], market_price, bid]
//   cp1[j] = prod_{k<j} rates[k]
//   out[0:B]  = cp1[bid]            (bid in [0,300])
//   out[B:2B] = cp1[mp] - cp1[mp+1] (mp  in [0,299])
//
// Persistent grid (148x16 blocks x 4 warps), DEPTH-2 software pipeline:
//   iter i: issue wave1(i+2) [tail + rounds 0,1, unconditional]
//           issue wave2(i+1) [rounds 2..4, predicated on mf(i+1), whose tail
//                             arrived one full iteration ago]
//           compute + store row i  [wave1 from 2 iters ago, wave2 from 1]
// -> every load has >= 1 iteration of slack; warp keeps 6-9 LDGs in flight.
// Interleaved ownership: lane t holds float2 chunks #(t+32k), k=0..4.
// cp1[x], x = 64q + r (warp-uniform):
//   m_t = c_q[t] * (2t<r ? vx_q : 1) * (2t+1<r ? vy_q : 1); butterfly-product.
// Skipped (early-exit) chunks = (1,1); never referenced by any query.

static constexpr int ROW    = 302;
static constexpr int ROWF2  = 151;               // float2 per row
static constexpr int WARPS  = 4;
static constexpr int BLOCKS = 148 * 16;
static constexpr int STRIDE = BLOCKS * WARPS;    // warps in grid (9472)
static constexpr unsigned FULL = 0xffffffffu;

struct QPre { float m, vx, vy; };

__device__ __forceinline__ QPre qpre(int x, int lane2,
                                     const float2& v0, const float2& v1,
                                     const float2& v2, const float2& v3,
                                     const float2& v4,
                                     float c1, float c2, float c3, float c4)
{
    const int q = x >> 6, r = x & 63;            // warp-uniform
    float cq = 1.0f;
    cq = (q == 1) ? c1 : cq;
    cq = (q == 2) ? c2 : cq;
    cq = (q == 3) ? c3 : cq;
    cq = (q == 4) ? c4 : cq;
    float vx = v0.x, vy = v0.y;
    vx = (q == 1) ? v1.x : vx;  vy = (q == 1) ? v1.y : vy;
    vx = (q == 2) ? v2.x : vx;  vy = (q == 2) ? v2.y : vy;
    vx = (q == 3) ? v3.x : vx;  vy = (q == 3) ? v3.y : vy;
    vx = (q == 4) ? v4.x : vx;  vy = (q == 4) ? v4.y : vy;
    float m = cq;
    m *= (lane2     < r) ? vx : 1.0f;
    m *= (lane2 + 1 < r) ? vy : 1.0f;
    return {m, vx, vy};
}

__global__ __launch_bounds__(128) void bidprefix_kernel(
    const float* __restrict__ in, float* __restrict__ out, int batch)
{
    const int lane  = threadIdx.x & 31;
    const int lane2 = 2 * lane;
    const int warp0 = blockIdx.x * WARPS + (threadIdx.x >> 5);

    const float2 zero = make_float2(0.f, 0.f);
    const float2 one  = make_float2(1.f, 1.f);

    // rotating row pointers; advance by constant STRIDE*ROWF2 float2 per slot
    int row0 = warp0;                             // current
    int row1 = warp0 + STRIDE;                    // next
    int row2 = warp0 + 2 * STRIDE;                // next-next
    const float2* R0 = reinterpret_cast<const float2*>(in) + (size_t)row0 * ROWF2;
    const float2* R1 = R0 + (size_t)STRIDE * ROWF2;
    const float2* R2 = R1 + (size_t)STRIDE * ROWF2;

    // ---- prologue ----
    // wave1(row0)
    float2 t0 = zero, a0 = zero, a1 = zero;
    if (row0 < batch) { t0 = R0[150]; a0 = R0[lane]; a1 = R0[lane + 32]; }
    // wave1(row1)
    float2 t1 = zero, b0 = zero, b1 = zero;
    if (row1 < batch) { t1 = R1[150]; b0 = R1[lane]; b1 = R1[lane + 32]; }
    // wave2(row0)
    const int mp0_ = (int)t0.x, bid0_ = (int)t0.y;
    int mf0 = (row0 < batch) ? (max(bid0_ - 1, mp0_) >> 1) : -1;
    float2 a2 = one, a3 = one, a4 = one;
    if (lane +  64 <= mf0) a2 = R0[lane +  64];
    if (lane +  96 <= mf0) a3 = R0[lane +  96];
    if (lane + 128 <= mf0) a4 = R0[lane + 128];

    while (row0 < batch) {
        // ---- issue wave1(row2) ----
        float2 t2 = zero, c0 = zero, c1v = zero;
        if (row2 < batch) { t2 = R2[150]; c0 = R2[lane]; c1v = R2[lane + 32]; }

        // ---- issue wave2(row1) (tail t1 arrived last iteration) ----
        const int mp1 = (int)t1.x, bid1 = (int)t1.y;
        const int mf1 = (row1 < batch) ? (max(bid1 - 1, mp1) >> 1) : -1;
        float2 b2 = one, b3 = one, b4 = one;
        if (lane +  64 <= mf1) b2 = R1[lane +  64];
        if (lane +  96 <= mf1) b3 = R1[lane +  96];
        if (lane + 128 <= mf1) b4 = R1[lane + 128];

        // ---- compute row0 (all its data long since in flight) ----
        const int mp  = (int)t0.x;                // 0..299
        const int bid = (int)t0.y;                // 0..300

        const float c1 = a0.x * a0.y;
        const float c2 = c1 * (a1.x * a1.y);
        const float c3 = c2 * (a2.x * a2.y);
        const float c4 = c3 * (a3.x * a3.y);

        const QPre sb = qpre(bid, lane2, a0, a1, a2, a3, a4, c1, c2, c3, c4);
        const QPre sm = qpre(mp,  lane2, a0, a1, a2, a3, a4, c1, c2, c3, c4);

        float m1 = sb.m, m2 = sm.m;
        #pragma unroll
        for (int off = 16; off; off >>= 1) {      // 2 chains pipeline SHFL lat
            const float w1 = __shfl_xor_sync(FULL, m1, off);
            const float w2 = __shfl_xor_sync(FULL, m2, off);
            m1 *= w1;
            m2 *= w2;
        }
        // m1 = cp1[bid], m2 = cp1[mp]

        const float rsel = (mp & 1) ? sm.vy : sm.vx;
        const float rmp  = __shfl_sync(FULL, rsel, (mp & 63) >> 1);

        if (lane == 0) {
            out[row0]         = m1;
            out[batch + row0] = m2 - m2 * rmp;    // cp1[mp] - cp1[mp+1]
        }

        // ---- rotate pipeline ----
        t0 = t1; a0 = b0; a1 = b1; a2 = b2; a3 = b3; a4 = b4;
        t1 = t2; b0 = c0; b1 = c1v;
        row0 = row1; row1 = row2; row2 += STRIDE;
        R0 = R1; R1 = R2; R2 += (size_t)STRIDE * ROWF2;
    }
}

extern "C" void kernel_launch(void* const* d_in, const int* in_sizes, int n_in,
                              void* d_out, int out_size)
{
    const float* in  = (const float*)d_in[0];
    float*       out = (float*)d_out;
    const int batch  = in_sizes[0] / ROW;         // 500000

    bidprefix_kernel<<<BLOCKS, 32 * WARPS>>>(in, out, batch);
}

// round 11
// speedup vs baseline: 1.1368x; 1.1368x over previous
#include <cuda_runtime.h>
#include <cstdint>

// BidPrefix: row = [rates[0..299], market_price, bid]
//   cp1[j] = prod_{k<j} rates[k]
//   out[0:B]  = cp1[bid]            (bid in [0,300])
//   out[B:2B] = cp1[mp] - cp1[mp+1] (mp  in [0,299])
//
// Block-staged metadata design. 64-thread block owns 32 consecutive rows:
//  S1: warp0 gathers the 32 row tails (MLP=32) -> smem; __syncthreads.
//  S2: each warp processes 16 rows. mf = max(bid-1,mp)>>1 comes from smem, so
//      ALL 5 rounds of rate loads are issued at once, each lane predicated
//      (minimum traffic, one DRAM wait per row, no tail->load serialization).
//  S3: results staged in smem, stored as 32-wide coalesced STG (no scattered
//      lane-0 write-allocate waste).
// Interleaved ownership: lane t holds float2 chunks #(t+32k), k=0..4.
// cp1[x], x = 64q + r (warp-uniform):
//   m_t = c_q[t] * (2t<r ? vx_q : 1) * (2t+1<r ? vy_q : 1); butterfly-product.
// Skipped (early-exit) chunks = (1,1); never referenced by any query.

static constexpr int ROW    = 302;
static constexpr int ROWF2  = 151;
static constexpr int RPB    = 32;              // rows per block
static constexpr int THREADS= 64;              // 2 warps, 16 rows each
static constexpr unsigned FULL = 0xffffffffu;

struct QPre { float m, vx, vy; };

__device__ __forceinline__ QPre qpre(int x, int lane2,
                                     const float2& v0, const float2& v1,
                                     const float2& v2, const float2& v3,
                                     const float2& v4,
                                     float c1, float c2, float c3, float c4)
{
    const int q = x >> 6, r = x & 63;          // warp-uniform
    float cq = 1.0f;
    cq = (q == 1) ? c1 : cq;
    cq = (q == 2) ? c2 : cq;
    cq = (q == 3) ? c3 : cq;
    cq = (q == 4) ? c4 : cq;
    float vx = v0.x, vy = v0.y;
    vx = (q == 1) ? v1.x : vx;  vy = (q == 1) ? v1.y : vy;
    vx = (q == 2) ? v2.x : vx;  vy = (q == 2) ? v2.y : vy;
    vx = (q == 3) ? v3.x : vx;  vy = (q == 3) ? v3.y : vy;
    vx = (q == 4) ? v4.x : vx;  vy = (q == 4) ? v4.y : vy;
    float m = cq;
    m *= (lane2     < r) ? vx : 1.0f;
    m *= (lane2 + 1 < r) ? vy : 1.0f;
    return {m, vx, vy};
}

__global__ __launch_bounds__(THREADS) void bidprefix_kernel(
    const float* __restrict__ in, float* __restrict__ out, int batch)
{
    __shared__ float2 meta[RPB];               // (mp, bid) per row
    __shared__ float  rs[RPB];                 // survival results
    __shared__ float  rl[RPB];                 // rate_last results

    const int tid   = threadIdx.x;
    const int lane  = tid & 31;
    const int wib   = tid >> 5;                // 0 or 1
    const int lane2 = 2 * lane;
    const int base  = blockIdx.x * RPB;

    // ---- stage 1: gather 32 tails (warp 0), MLP = 32 ----
    if (tid < RPB) {
        const int r = base + tid;
        float2 t = make_float2(0.f, 0.f);
        if (r < batch)
            t = reinterpret_cast<const float2*>(in)[(size_t)r * ROWF2 + 150];
        meta[tid] = t;
    }
    __syncthreads();

    // ---- stage 2: each warp processes 16 rows ----
    const int rbeg = 16 * wib;                 // row-in-block range [rbeg, rbeg+16)
    const float2* P = reinterpret_cast<const float2*>(in)
                    + (size_t)(base + rbeg) * ROWF2;
    const float2 one = make_float2(1.f, 1.f);

    #pragma unroll 1
    for (int j = 0; j < 16; ++j, P += ROWF2) {
        const int rloc = rbeg + j;
        if (base + rloc >= batch) break;

        const float2 t = meta[rloc];           // broadcast LDS
        const int mp  = (int)t.x;              // 0..299
        const int bid = (int)t.y;              // 0..300
        const int mf  = max(bid - 1, mp) >> 1; // last float2 chunk needed

        // all rounds issued together, per-lane predicated (min traffic, MLP=5)
        float2 v0 = one, v1 = one, v2 = one, v3 = one, v4 = one;
        if (lane       <= mf) v0 = P[lane];
        if (lane +  32 <= mf) v1 = P[lane +  32];
        if (lane +  64 <= mf) v2 = P[lane +  64];
        if (lane +  96 <= mf) v3 = P[lane +  96];
        if (lane + 128 <= mf) v4 = P[lane + 128];

        // vertical chain: c_j = prod over rounds < j of (vx*vy)
        const float c1 = v0.x * v0.y;
        const float c2 = c1 * (v1.x * v1.y);
        const float c3 = c2 * (v2.x * v2.y);
        const float c4 = c3 * (v3.x * v3.y);

        const QPre sb = qpre(bid, lane2, v0, v1, v2, v3, v4, c1, c2, c3, c4);
        const QPre sm = qpre(mp,  lane2, v0, v1, v2, v3, v4, c1, c2, c3, c4);

        float m1 = sb.m, m2 = sm.m;
        #pragma unroll
        for (int off = 16; off; off >>= 1) {   // 2 chains pipeline SHFL latency
            const float w1 = __shfl_xor_sync(FULL, m1, off);
            const float w2 = __shfl_xor_sync(FULL, m2, off);
            m1 *= w1;
            m2 *= w2;
        }
        // m1 = cp1[bid], m2 = cp1[mp] in every lane

        const float rsel = (mp & 1) ? sm.vy : sm.vx;
        const float rmp  = __shfl_sync(FULL, rsel, (mp & 63) >> 1);

        if (lane == 0) {
            rs[rloc] = m1;
            rl[rloc] = m2 - m2 * rmp;          // cp1[mp] - cp1[mp+1]
        }
    }
    __syncthreads();

    // ---- stage 3: coalesced 32-wide output stores ----
    if (tid < RPB) {
        const int r = base + tid;
        if (r < batch) {
            out[r]         = rs[tid];
            out[batch + r] = rl[tid];
        }
    }
}

extern "C" void kernel_launch(void* const* d_in, const int* in_sizes, int n_in,
                              void* d_out, int out_size)
{
    const float* in  = (const float*)d_in[0];
    float*       out = (float*)d_out;
    const int batch  = in_sizes[0] / ROW;      // 500000

    const int blocks = (batch + RPB - 1) / RPB;   // 15625
    bidprefix_kernel<<<blocks, THREADS>>>(in, out, batch);
}